// round 1
// baseline (speedup 1.0000x reference)
#include <cuda_runtime.h>

// Problem shape (fixed per dataset)
#define NN   50000
#define EE_CAP 1650512   // E + N self loops, with margin
#define D    128
#define DOUT 64

// ---- device scratch (no allocation allowed) ----
__device__ float g_h[NN * D];       // current-layer transformed features h = x @ W
__device__ float g_x[NN * D];       // aggregation output / next layer input
__device__ float g_ssrc[NN];        // h @ att_src
__device__ float g_sdst[NN];        // h @ att_dst
__device__ int   g_deg[NN];
__device__ int   g_offs[NN + 1];
__device__ int   g_cursor[NN];
__device__ int   g_esrc[EE_CAP];    // CSR-by-dst: source node per edge

// ---------------------------------------------------------------- CSR build
__global__ void zero_deg_kernel(int n) {
    int i = blockIdx.x * blockDim.x + threadIdx.x;
    if (i < n) g_deg[i] = 0;
}

__global__ void hist_kernel(const int* __restrict__ ei, int E, int n) {
    int i = blockIdx.x * blockDim.x + threadIdx.x;
    if (i < E) {
        atomicAdd(&g_deg[ei[E + i]], 1);        // dst row of edge_index
    } else if (i < E + n) {
        atomicAdd(&g_deg[i - E], 1);            // self loop
    }
}

// single-block exclusive scan over g_deg -> g_offs, g_cursor
__global__ void scan_kernel(int n) {
    __shared__ int sums[1024];
    int t = threadIdx.x;
    int chunk = (n + 1023) >> 10;
    int b = t * chunk;
    int e = min(b + chunk, n);
    int s = 0;
    for (int i = b; i < e; i++) s += g_deg[i];
    sums[t] = s;
    __syncthreads();
    for (int off = 1; off < 1024; off <<= 1) {
        int v = 0;
        if (t >= off) v = sums[t - off];
        __syncthreads();
        sums[t] += v;
        __syncthreads();
    }
    int run = (t == 0) ? 0 : sums[t - 1];
    for (int i = b; i < e; i++) {
        g_offs[i] = run;
        g_cursor[i] = run;
        run += g_deg[i];
    }
    if (t == 1023) g_offs[n] = sums[1023];
}

__global__ void scatter_kernel(const int* __restrict__ ei, int E, int n) {
    int i = blockIdx.x * blockDim.x + threadIdx.x;
    if (i < E) {
        int s = ei[i];
        int d = ei[E + i];
        int p = atomicAdd(&g_cursor[d], 1);
        g_esrc[p] = s;
    } else if (i < E + n) {
        int v = i - E;
        int p = atomicAdd(&g_cursor[v], 1);
        g_esrc[p] = v;
    }
}

// ---------------------------------------------------------------- GEMM
// Y[n, COLS] = X[n, 128] @ W[128, COLS] (+ bias). Block = COLS threads,
// 32 rows per block, thread computes 8 rows x 4 cols from smem.
template <int COLS>
__global__ void gemm_kernel(const float* __restrict__ X, const float* __restrict__ W,
                            const float* __restrict__ bias, float* __restrict__ Y, int n) {
    extern __shared__ float sm[];
    float* Ws = sm;              // D * COLS
    float* Xs = sm + D * COLS;   // 32 * D
    const int CG = COLS / 4;
    int tid = threadIdx.x;
    int cg = tid % CG;
    int rg = tid / CG;           // 0..3
    int rowbase = blockIdx.x * 32;

    for (int i = tid; i < D * COLS; i += COLS) Ws[i] = W[i];
    for (int i = tid; i < 32 * D; i += COLS) {
        int r = rowbase + (i >> 7);
        Xs[i] = (r < n) ? X[(size_t)r * D + (i & 127)] : 0.f;
    }
    __syncthreads();

    float4 acc[8];
#pragma unroll
    for (int r = 0; r < 8; r++) acc[r] = make_float4(0.f, 0.f, 0.f, 0.f);

#pragma unroll 4
    for (int k = 0; k < D; k++) {
        float4 w4 = *(const float4*)&Ws[k * COLS + cg * 4];
#pragma unroll
        for (int rr = 0; rr < 8; rr++) {
            float xv = Xs[(rg * 8 + rr) * D + k];
            acc[rr].x += xv * w4.x;
            acc[rr].y += xv * w4.y;
            acc[rr].z += xv * w4.z;
            acc[rr].w += xv * w4.w;
        }
    }

    float4 b4 = make_float4(0.f, 0.f, 0.f, 0.f);
    if (bias) b4 = *(const float4*)&bias[cg * 4];
#pragma unroll
    for (int rr = 0; rr < 8; rr++) {
        int r = rowbase + rg * 8 + rr;
        if (r < n) {
            float4 o;
            o.x = acc[rr].x + b4.x;
            o.y = acc[rr].y + b4.y;
            o.z = acc[rr].z + b4.z;
            o.w = acc[rr].w + b4.w;
            *(float4*)&Y[(size_t)r * COLS + cg * 4] = o;
        }
    }
}

// ---------------------------------------------------------------- attention dots
// per node: s_src = h . att_src, s_dst = h . att_dst (one warp per node)
__global__ void dots_kernel(const float* __restrict__ h,
                            const float* __restrict__ asrc,
                            const float* __restrict__ adst, int n) {
    int gt = blockIdx.x * blockDim.x + threadIdx.x;
    int w = gt >> 5, lane = gt & 31;
    if (w >= n) return;
    float4 hv = *(const float4*)&h[(size_t)w * D + lane * 4];
    float4 a = *(const float4*)&asrc[lane * 4];
    float4 b = *(const float4*)&adst[lane * 4];
    float p = hv.x * a.x + hv.y * a.y + hv.z * a.z + hv.w * a.w;
    float q = hv.x * b.x + hv.y * b.y + hv.z * b.z + hv.w * b.w;
#pragma unroll
    for (int o = 16; o; o >>= 1) {
        p += __shfl_xor_sync(0xffffffffu, p, o);
        q += __shfl_xor_sync(0xffffffffu, q, o);
    }
    if (lane == 0) {
        g_ssrc[w] = p;
        g_sdst[w] = q;
    }
}

// ---------------------------------------------------------------- aggregation
// One warp per destination node. Pass 1: segment max of relu(e).
// Pass 2: exp/sum + feature accumulation (alpha broadcast via shfl).
__global__ void __launch_bounds__(256) aggregate_kernel(
    const float* __restrict__ h, const float* __restrict__ bias,
    float* __restrict__ out, int n, int do_relu) {
    int gt = blockIdx.x * blockDim.x + threadIdx.x;
    int node = gt >> 5, lane = gt & 31;
    if (node >= n) return;

    int beg = g_offs[node];
    int end = g_offs[node + 1];
    float sd = g_sdst[node];

    // pass 1: max of relu(e) over incoming edges
    float m = -1e30f;
    for (int j = beg + lane; j < end; j += 32) {
        float e = fmaxf(g_ssrc[g_esrc[j]] + sd, 0.f);
        m = fmaxf(m, e);
    }
#pragma unroll
    for (int o = 16; o; o >>= 1) m = fmaxf(m, __shfl_xor_sync(0xffffffffu, m, o));

    // pass 2: exp-sum + weighted feature accumulation
    float4 acc = make_float4(0.f, 0.f, 0.f, 0.f);
    float denom = 0.f;
    for (int base = beg; base < end; base += 32) {
        int j = base + lane;
        float ex = 0.f;
        int s = 0;
        if (j < end) {
            s = g_esrc[j];
            ex = __expf(fmaxf(g_ssrc[s] + sd, 0.f) - m);
        }
        denom += ex;
        int cnt = min(32, end - base);
        for (int k = 0; k < cnt; k++) {
            float wgt = __shfl_sync(0xffffffffu, ex, k);
            int sk = __shfl_sync(0xffffffffu, s, k);
            const float4 hv = *(const float4*)&h[(size_t)sk * D + lane * 4];
            acc.x += wgt * hv.x;
            acc.y += wgt * hv.y;
            acc.z += wgt * hv.z;
            acc.w += wgt * hv.w;
        }
    }
#pragma unroll
    for (int o = 16; o; o >>= 1) denom += __shfl_xor_sync(0xffffffffu, denom, o);

    float inv = 1.f / denom;
    float4 b4 = *(const float4*)&bias[lane * 4];
    float4 o4;
    o4.x = acc.x * inv + b4.x;
    o4.y = acc.y * inv + b4.y;
    o4.z = acc.z * inv + b4.z;
    o4.w = acc.w * inv + b4.w;
    if (do_relu) {
        o4.x = fmaxf(o4.x, 0.f);
        o4.y = fmaxf(o4.y, 0.f);
        o4.z = fmaxf(o4.z, 0.f);
        o4.w = fmaxf(o4.w, 0.f);
    }
    *(float4*)&out[(size_t)node * D + lane * 4] = o4;
}

// ---------------------------------------------------------------- launch
extern "C" void kernel_launch(void* const* d_in, const int* in_sizes, int n_in,
                              void* d_out, int out_size) {
    const float* node_x = (const float*)d_in[0];
    const int*   ei     = (const int*)d_in[1];
    const float* W1     = (const float*)d_in[2];
    const float* as1    = (const float*)d_in[3];
    const float* ad1    = (const float*)d_in[4];
    const float* b1     = (const float*)d_in[5];
    const float* W2     = (const float*)d_in[6];
    const float* as2    = (const float*)d_in[7];
    const float* ad2    = (const float*)d_in[8];
    const float* b2     = (const float*)d_in[9];
    const float* Wout   = (const float*)d_in[10];
    const float* bout   = (const float*)d_in[11];
    float* out = (float*)d_out;

    int n = in_sizes[0] / D;       // 50000
    int E = in_sizes[1] / 2;       // 1600000

    float *h_ptr, *x_ptr;
    cudaGetSymbolAddress((void**)&h_ptr, g_h);
    cudaGetSymbolAddress((void**)&x_ptr, g_x);

    const int SMEM128 = (D * 128 + 32 * D) * (int)sizeof(float);   // 80 KB
    const int SMEM64  = (D * 64 + 32 * D) * (int)sizeof(float);    // 48 KB
    cudaFuncSetAttribute(gemm_kernel<128>, cudaFuncAttributeMaxDynamicSharedMemorySize, SMEM128);
    cudaFuncSetAttribute(gemm_kernel<64>, cudaFuncAttributeMaxDynamicSharedMemorySize, SMEM64);

    int tot = E + n;

    // CSR build (shared by both layers)
    zero_deg_kernel<<<(n + 255) / 256, 256>>>(n);
    hist_kernel<<<(tot + 255) / 256, 256>>>(ei, E, n);
    scan_kernel<<<1, 1024>>>(n);
    scatter_kernel<<<(tot + 255) / 256, 256>>>(ei, E, n);

    int agg_grid = (n * 32 + 255) / 256;
    int dot_grid = agg_grid;
    int gemm_grid = (n + 31) / 32;

    // layer 1
    gemm_kernel<128><<<gemm_grid, 128, SMEM128>>>(node_x, W1, nullptr, h_ptr, n);
    dots_kernel<<<dot_grid, 256>>>(h_ptr, as1, ad1, n);
    aggregate_kernel<<<agg_grid, 256>>>(h_ptr, b1, x_ptr, n, 1);

    // layer 2
    gemm_kernel<128><<<gemm_grid, 128, SMEM128>>>(x_ptr, W2, nullptr, h_ptr, n);
    dots_kernel<<<dot_grid, 256>>>(h_ptr, as2, ad2, n);
    aggregate_kernel<<<agg_grid, 256>>>(h_ptr, b2, x_ptr, n, 0);

    // output linear
    gemm_kernel<64><<<gemm_grid, 64, SMEM64>>>(x_ptr, Wout, bout, out, n);
}

// round 2
// speedup vs baseline: 1.0546x; 1.0546x over previous
#include <cuda_runtime.h>
#include <cuda_fp16.h>

// Problem shape (fixed per dataset)
#define NN   50000
#define EE_CAP 1650512   // E + N self loops, with margin
#define D    128
#define DOUT 64

// ---- device scratch (no allocation allowed) ----
__device__ float  g_h[NN * D];      // current-layer transformed features h = x @ W (fp32)
__device__ __half g_hh[NN * D];     // fp16 copy of h for the edge gather
__device__ float  g_x[NN * D];      // aggregation output / next layer input
__device__ float  g_ssrc[NN];       // h @ att_src
__device__ float  g_sdst[NN];       // h @ att_dst
__device__ int    g_deg[NN];
__device__ int    g_offs[NN + 1];
__device__ int    g_cursor[NN];
__device__ int    g_esrc[EE_CAP];   // CSR-by-dst: source node per edge

// ---------------------------------------------------------------- CSR build
__global__ void zero_deg_kernel(int n) {
    int i = blockIdx.x * blockDim.x + threadIdx.x;
    if (i < n) g_deg[i] = 0;
}

__global__ void hist_kernel(const int* __restrict__ ei, int E, int n) {
    int i = blockIdx.x * blockDim.x + threadIdx.x;
    if (i < E) {
        atomicAdd(&g_deg[ei[E + i]], 1);        // dst row of edge_index
    } else if (i < E + n) {
        atomicAdd(&g_deg[i - E], 1);            // self loop
    }
}

// single-block exclusive scan over g_deg -> g_offs, g_cursor
__global__ void scan_kernel(int n) {
    __shared__ int sums[1024];
    int t = threadIdx.x;
    int chunk = (n + 1023) >> 10;
    int b = t * chunk;
    int e = min(b + chunk, n);
    int s = 0;
    for (int i = b; i < e; i++) s += g_deg[i];
    sums[t] = s;
    __syncthreads();
    for (int off = 1; off < 1024; off <<= 1) {
        int v = 0;
        if (t >= off) v = sums[t - off];
        __syncthreads();
        sums[t] += v;
        __syncthreads();
    }
    int run = (t == 0) ? 0 : sums[t - 1];
    for (int i = b; i < e; i++) {
        g_offs[i] = run;
        g_cursor[i] = run;
        run += g_deg[i];
    }
    if (t == 1023) g_offs[n] = sums[1023];
}

__global__ void scatter_kernel(const int* __restrict__ ei, int E, int n) {
    int i = blockIdx.x * blockDim.x + threadIdx.x;
    if (i < E) {
        int s = ei[i];
        int d = ei[E + i];
        int p = atomicAdd(&g_cursor[d], 1);
        g_esrc[p] = s;
    } else if (i < E + n) {
        int v = i - E;
        int p = atomicAdd(&g_cursor[v], 1);
        g_esrc[p] = v;
    }
}

// ---------------------------------------------------------------- GEMM
// Y[n, COLS] = X[n, 128] @ W[128, COLS] (+ bias). Block = COLS threads,
// 32 rows per block, thread computes 8 rows x 4 cols from smem.
// Optionally also emits a fp16 copy Yh (for the aggregation gather).
template <int COLS>
__global__ void gemm_kernel(const float* __restrict__ X, const float* __restrict__ W,
                            const float* __restrict__ bias, float* __restrict__ Y,
                            __half* __restrict__ Yh, int n) {
    extern __shared__ float sm[];
    float* Ws = sm;              // D * COLS
    float* Xs = sm + D * COLS;   // 32 * D
    const int CG = COLS / 4;
    int tid = threadIdx.x;
    int cg = tid % CG;
    int rg = tid / CG;           // 0..3
    int rowbase = blockIdx.x * 32;

    for (int i = tid; i < D * COLS; i += COLS) Ws[i] = W[i];
    for (int i = tid; i < 32 * D; i += COLS) {
        int r = rowbase + (i >> 7);
        Xs[i] = (r < n) ? X[(size_t)r * D + (i & 127)] : 0.f;
    }
    __syncthreads();

    float4 acc[8];
#pragma unroll
    for (int r = 0; r < 8; r++) acc[r] = make_float4(0.f, 0.f, 0.f, 0.f);

#pragma unroll 4
    for (int k = 0; k < D; k++) {
        float4 w4 = *(const float4*)&Ws[k * COLS + cg * 4];
#pragma unroll
        for (int rr = 0; rr < 8; rr++) {
            float xv = Xs[(rg * 8 + rr) * D + k];
            acc[rr].x += xv * w4.x;
            acc[rr].y += xv * w4.y;
            acc[rr].z += xv * w4.z;
            acc[rr].w += xv * w4.w;
        }
    }

    float4 b4 = make_float4(0.f, 0.f, 0.f, 0.f);
    if (bias) b4 = *(const float4*)&bias[cg * 4];
#pragma unroll
    for (int rr = 0; rr < 8; rr++) {
        int r = rowbase + rg * 8 + rr;
        if (r < n) {
            float4 o;
            o.x = acc[rr].x + b4.x;
            o.y = acc[rr].y + b4.y;
            o.z = acc[rr].z + b4.z;
            o.w = acc[rr].w + b4.w;
            *(float4*)&Y[(size_t)r * COLS + cg * 4] = o;
            if (Yh) {
                __half2 h0 = __floats2half2_rn(o.x, o.y);
                __half2 h1 = __floats2half2_rn(o.z, o.w);
                uint2 packed;
                packed.x = *(unsigned*)&h0;
                packed.y = *(unsigned*)&h1;
                *(uint2*)&Yh[(size_t)r * COLS + cg * 4] = packed;
            }
        }
    }
}

// ---------------------------------------------------------------- attention dots
// per node: s_src = h . att_src, s_dst = h . att_dst (one warp per node)
__global__ void dots_kernel(const float* __restrict__ h,
                            const float* __restrict__ asrc,
                            const float* __restrict__ adst, int n) {
    int gt = blockIdx.x * blockDim.x + threadIdx.x;
    int w = gt >> 5, lane = gt & 31;
    if (w >= n) return;
    float4 hv = *(const float4*)&h[(size_t)w * D + lane * 4];
    float4 a = *(const float4*)&asrc[lane * 4];
    float4 b = *(const float4*)&adst[lane * 4];
    float p = hv.x * a.x + hv.y * a.y + hv.z * a.z + hv.w * a.w;
    float q = hv.x * b.x + hv.y * b.y + hv.z * b.z + hv.w * b.w;
#pragma unroll
    for (int o = 16; o; o >>= 1) {
        p += __shfl_xor_sync(0xffffffffu, p, o);
        q += __shfl_xor_sync(0xffffffffu, q, o);
    }
    if (lane == 0) {
        g_ssrc[w] = p;
        g_sdst[w] = q;
    }
}

// ---------------------------------------------------------------- aggregation
// One warp per destination node, single pass. Since NEG_SLOPE=0, e >= 0 and
// the softmax max-shift is unnecessary (exp(e) <= exp(~15), fp32-safe;
// alpha ratios are mathematically identical to the max-shifted form).
// Feature rows are gathered from the fp16 copy g_hh (halves the dominant
// L2 stream). Gather loop unrolled 4-wide for memory-level parallelism.
__global__ void __launch_bounds__(256) aggregate_kernel(
    const __half* __restrict__ hh, const float* __restrict__ bias,
    float* __restrict__ out, int n, int do_relu) {
    int gt = blockIdx.x * blockDim.x + threadIdx.x;
    int node = gt >> 5, lane = gt & 31;
    if (node >= n) return;

    int beg = g_offs[node];
    int end = g_offs[node + 1];
    float sd = g_sdst[node];

    float2 accA = make_float2(0.f, 0.f);
    float2 accB = make_float2(0.f, 0.f);
    float denom = 0.f;

    for (int base = beg; base < end; base += 32) {
        int j = base + lane;
        float ex = 0.f;
        int s = 0;
        if (j < end) {
            s = g_esrc[j];
            ex = __expf(fmaxf(g_ssrc[s] + sd, 0.f));
        }
        denom += ex;
        int cnt = min(32, end - base);
        int k = 0;
        for (; k + 4 <= cnt; k += 4) {
            float w0 = __shfl_sync(0xffffffffu, ex, k + 0);
            float w1 = __shfl_sync(0xffffffffu, ex, k + 1);
            float w2 = __shfl_sync(0xffffffffu, ex, k + 2);
            float w3 = __shfl_sync(0xffffffffu, ex, k + 3);
            int s0 = __shfl_sync(0xffffffffu, s, k + 0);
            int s1 = __shfl_sync(0xffffffffu, s, k + 1);
            int s2 = __shfl_sync(0xffffffffu, s, k + 2);
            int s3 = __shfl_sync(0xffffffffu, s, k + 3);
            uint2 v0 = *(const uint2*)&hh[(size_t)s0 * D + lane * 4];
            uint2 v1 = *(const uint2*)&hh[(size_t)s1 * D + lane * 4];
            uint2 v2 = *(const uint2*)&hh[(size_t)s2 * D + lane * 4];
            uint2 v3 = *(const uint2*)&hh[(size_t)s3 * D + lane * 4];
            float2 a0 = __half22float2(*(__half2*)&v0.x);
            float2 b0 = __half22float2(*(__half2*)&v0.y);
            float2 a1 = __half22float2(*(__half2*)&v1.x);
            float2 b1 = __half22float2(*(__half2*)&v1.y);
            float2 a2 = __half22float2(*(__half2*)&v2.x);
            float2 b2 = __half22float2(*(__half2*)&v2.y);
            float2 a3 = __half22float2(*(__half2*)&v3.x);
            float2 b3 = __half22float2(*(__half2*)&v3.y);
            accA.x += w0 * a0.x + w1 * a1.x + w2 * a2.x + w3 * a3.x;
            accA.y += w0 * a0.y + w1 * a1.y + w2 * a2.y + w3 * a3.y;
            accB.x += w0 * b0.x + w1 * b1.x + w2 * b2.x + w3 * b3.x;
            accB.y += w0 * b0.y + w1 * b1.y + w2 * b2.y + w3 * b3.y;
        }
        for (; k < cnt; k++) {
            float wk = __shfl_sync(0xffffffffu, ex, k);
            int sk = __shfl_sync(0xffffffffu, s, k);
            uint2 v = *(const uint2*)&hh[(size_t)sk * D + lane * 4];
            float2 a = __half22float2(*(__half2*)&v.x);
            float2 b = __half22float2(*(__half2*)&v.y);
            accA.x += wk * a.x;
            accA.y += wk * a.y;
            accB.x += wk * b.x;
            accB.y += wk * b.y;
        }
    }
#pragma unroll
    for (int o = 16; o; o >>= 1) denom += __shfl_xor_sync(0xffffffffu, denom, o);

    float inv = 1.f / denom;
    float4 b4 = *(const float4*)&bias[lane * 4];
    float4 o4;
    o4.x = accA.x * inv + b4.x;
    o4.y = accA.y * inv + b4.y;
    o4.z = accB.x * inv + b4.z;
    o4.w = accB.y * inv + b4.w;
    if (do_relu) {
        o4.x = fmaxf(o4.x, 0.f);
        o4.y = fmaxf(o4.y, 0.f);
        o4.z = fmaxf(o4.z, 0.f);
        o4.w = fmaxf(o4.w, 0.f);
    }
    *(float4*)&out[(size_t)node * D + lane * 4] = o4;
}

// ---------------------------------------------------------------- launch
extern "C" void kernel_launch(void* const* d_in, const int* in_sizes, int n_in,
                              void* d_out, int out_size) {
    const float* node_x = (const float*)d_in[0];
    const int*   ei     = (const int*)d_in[1];
    const float* W1     = (const float*)d_in[2];
    const float* as1    = (const float*)d_in[3];
    const float* ad1    = (const float*)d_in[4];
    const float* b1     = (const float*)d_in[5];
    const float* W2     = (const float*)d_in[6];
    const float* as2    = (const float*)d_in[7];
    const float* ad2    = (const float*)d_in[8];
    const float* b2     = (const float*)d_in[9];
    const float* Wout   = (const float*)d_in[10];
    const float* bout   = (const float*)d_in[11];
    float* out = (float*)d_out;

    int n = in_sizes[0] / D;       // 50000
    int E = in_sizes[1] / 2;       // 1600000

    float *h_ptr, *x_ptr;
    __half* hh_ptr;
    cudaGetSymbolAddress((void**)&h_ptr, g_h);
    cudaGetSymbolAddress((void**)&x_ptr, g_x);
    cudaGetSymbolAddress((void**)&hh_ptr, g_hh);

    const int SMEM128 = (D * 128 + 32 * D) * (int)sizeof(float);   // 80 KB
    const int SMEM64  = (D * 64 + 32 * D) * (int)sizeof(float);    // 48 KB
    cudaFuncSetAttribute(gemm_kernel<128>, cudaFuncAttributeMaxDynamicSharedMemorySize, SMEM128);
    cudaFuncSetAttribute(gemm_kernel<64>, cudaFuncAttributeMaxDynamicSharedMemorySize, SMEM64);

    int tot = E + n;

    // CSR build (shared by both layers)
    zero_deg_kernel<<<(n + 255) / 256, 256>>>(n);
    hist_kernel<<<(tot + 255) / 256, 256>>>(ei, E, n);
    scan_kernel<<<1, 1024>>>(n);
    scatter_kernel<<<(tot + 255) / 256, 256>>>(ei, E, n);

    int agg_grid = (n * 32 + 255) / 256;
    int dot_grid = agg_grid;
    int gemm_grid = (n + 31) / 32;

    // layer 1
    gemm_kernel<128><<<gemm_grid, 128, SMEM128>>>(node_x, W1, nullptr, h_ptr, hh_ptr, n);
    dots_kernel<<<dot_grid, 256>>>(h_ptr, as1, ad1, n);
    aggregate_kernel<<<agg_grid, 256>>>(hh_ptr, b1, x_ptr, n, 1);

    // layer 2
    gemm_kernel<128><<<gemm_grid, 128, SMEM128>>>(x_ptr, W2, nullptr, h_ptr, hh_ptr, n);
    dots_kernel<<<dot_grid, 256>>>(h_ptr, as2, ad2, n);
    aggregate_kernel<<<agg_grid, 256>>>(hh_ptr, b2, x_ptr, n, 0);

    // output linear
    gemm_kernel<64><<<gemm_grid, 64, SMEM64>>>(x_ptr, Wout, bout, out, nullptr, n);
}

// round 3
// speedup vs baseline: 1.0869x; 1.0306x over previous
#include <cuda_runtime.h>
#include <cuda_fp16.h>

// Problem shape (fixed per dataset)
#define NN   50000
#define EE_CAP 1650512   // E + N self loops, with margin
#define D    128
#define DOUT 64

// ---- device scratch (no allocation allowed) ----
__device__ float  g_h[NN * D];      // current-layer transformed features h = x @ W (fp32)
__device__ float  g_x[NN * D];      // aggregation output / next layer input
__device__ float  g_ssrc[NN];       // h @ att_src
__device__ float  g_sdst[NN];       // h @ att_dst
__device__ int    g_deg[NN];
__device__ int    g_offs[NN + 1];
__device__ int    g_cursor[NN];
__device__ int    g_esrc[EE_CAP];   // CSR-by-dst: source node per edge
__device__ float2 g_epack[EE_CAP];  // per edge: {src as int bits, normalized alpha}

// packed f32x2 fma: acc += a * b (two fp32 lanes per instruction)
__device__ __forceinline__ void ffma2(unsigned long long& acc,
                                      unsigned long long a,
                                      unsigned long long b) {
    asm("fma.rn.f32x2 %0, %1, %2, %0;" : "+l"(acc) : "l"(a), "l"(b));
}
__device__ __forceinline__ unsigned long long dup2(float v) {
    unsigned long long r;
    asm("mov.b64 %0, {%1, %1};" : "=l"(r) : "f"(v));
    return r;
}

// ---------------------------------------------------------------- CSR build
__global__ void zero_deg_kernel(int n) {
    int i = blockIdx.x * blockDim.x + threadIdx.x;
    if (i < n) g_deg[i] = 0;
}

// 4 edges per thread for atomic MLP
__global__ void hist_kernel(const int* __restrict__ ei, int E, int n) {
    int i0 = (blockIdx.x * blockDim.x + threadIdx.x) * 4;
#pragma unroll
    for (int u = 0; u < 4; u++) {
        int i = i0 + u;
        if (i < E) atomicAdd(&g_deg[ei[E + i]], 1);
        else if (i < E + n) atomicAdd(&g_deg[i - E], 1);
    }
}

// single-block exclusive scan over g_deg -> g_offs, g_cursor
__global__ void scan_kernel(int n) {
    __shared__ int sums[1024];
    int t = threadIdx.x;
    int chunk = (n + 1023) >> 10;
    int b = t * chunk;
    int e = min(b + chunk, n);
    int s = 0;
    for (int i = b; i < e; i++) s += g_deg[i];
    sums[t] = s;
    __syncthreads();
    for (int off = 1; off < 1024; off <<= 1) {
        int v = 0;
        if (t >= off) v = sums[t - off];
        __syncthreads();
        sums[t] += v;
        __syncthreads();
    }
    int run = (t == 0) ? 0 : sums[t - 1];
    for (int i = b; i < e; i++) {
        g_offs[i] = run;
        g_cursor[i] = run;
        run += g_deg[i];
    }
    if (t == 1023) g_offs[n] = sums[1023];
}

// 4 edges per thread
__global__ void scatter_kernel(const int* __restrict__ ei, int E, int n) {
    int i0 = (blockIdx.x * blockDim.x + threadIdx.x) * 4;
#pragma unroll
    for (int u = 0; u < 4; u++) {
        int i = i0 + u;
        if (i < E) {
            int s = ei[i];
            int d = ei[E + i];
            int p = atomicAdd(&g_cursor[d], 1);
            g_esrc[p] = s;
        } else if (i < E + n) {
            int v = i - E;
            int p = atomicAdd(&g_cursor[v], 1);
            g_esrc[p] = v;
        }
    }
}

// ---------------------------------------------------------------- GEMM
// Y[n, COLS] = X[n, 128] @ W[128, COLS] (+ bias). Block = COLS threads,
// 32 rows per block, thread computes 8 rows x 4 cols (as 2 f32x2 pairs).
template <int COLS>
__global__ void gemm_kernel(const float* __restrict__ X, const float* __restrict__ W,
                            const float* __restrict__ bias, float* __restrict__ Y, int n) {
    extern __shared__ float sm[];
    float* Ws = sm;              // D * COLS
    float* Xs = sm + D * COLS;   // 32 * D
    const int CG = COLS / 4;
    int tid = threadIdx.x;
    int cg = tid % CG;
    int rg = tid / CG;           // 0..3
    int rowbase = blockIdx.x * 32;

    for (int i = tid; i < D * COLS; i += COLS) Ws[i] = W[i];
    for (int i = tid; i < 32 * D; i += COLS) {
        int r = rowbase + (i >> 7);
        Xs[i] = (r < n) ? X[(size_t)r * D + (i & 127)] : 0.f;
    }
    __syncthreads();

    unsigned long long accL[8], accH[8];
#pragma unroll
    for (int r = 0; r < 8; r++) { accL[r] = 0ull; accH[r] = 0ull; }

#pragma unroll 4
    for (int k = 0; k < D; k++) {
        ulonglong2 w2 = *(const ulonglong2*)&Ws[k * COLS + cg * 4];
#pragma unroll
        for (int rr = 0; rr < 8; rr++) {
            unsigned long long xx = dup2(Xs[(rg * 8 + rr) * D + k]);
            ffma2(accL[rr], xx, w2.x);
            ffma2(accH[rr], xx, w2.y);
        }
    }

    float4 b4 = make_float4(0.f, 0.f, 0.f, 0.f);
    if (bias) b4 = *(const float4*)&bias[cg * 4];
#pragma unroll
    for (int rr = 0; rr < 8; rr++) {
        int r = rowbase + rg * 8 + rr;
        if (r < n) {
            float2 lo = *(float2*)&accL[rr];
            float2 hi = *(float2*)&accH[rr];
            float4 o;
            o.x = lo.x + b4.x;
            o.y = lo.y + b4.y;
            o.z = hi.x + b4.z;
            o.w = hi.y + b4.w;
            *(float4*)&Y[(size_t)r * COLS + cg * 4] = o;
        }
    }
}

// ---------------------------------------------------------------- attention dots
// per node: s_src = h . att_src, s_dst = h . att_dst (one warp per node)
__global__ void dots_kernel(const float* __restrict__ h,
                            const float* __restrict__ asrc,
                            const float* __restrict__ adst, int n) {
    int gt = blockIdx.x * blockDim.x + threadIdx.x;
    int w = gt >> 5, lane = gt & 31;
    if (w >= n) return;
    float4 hv = *(const float4*)&h[(size_t)w * D + lane * 4];
    float4 a = *(const float4*)&asrc[lane * 4];
    float4 b = *(const float4*)&adst[lane * 4];
    float p = hv.x * a.x + hv.y * a.y + hv.z * a.z + hv.w * a.w;
    float q = hv.x * b.x + hv.y * b.y + hv.z * b.z + hv.w * b.w;
#pragma unroll
    for (int o = 16; o; o >>= 1) {
        p += __shfl_xor_sync(0xffffffffu, p, o);
        q += __shfl_xor_sync(0xffffffffu, q, o);
    }
    if (lane == 0) {
        g_ssrc[w] = p;
        g_sdst[w] = q;
    }
}

// ---------------------------------------------------------------- alpha precompute
// One warp per destination node: compute exp(relu(e)) per incoming edge,
// warp-reduce the denominator, write packed {src_bits, alpha_normalized}.
// (NEG_SLOPE=0 => e >= 0, exp bounded, max-shift unnecessary.)
__global__ void __launch_bounds__(256) alpha_kernel(int n) {
    int gt = blockIdx.x * blockDim.x + threadIdx.x;
    int node = gt >> 5, lane = gt & 31;
    if (node >= n) return;
    int beg = g_offs[node];
    int end = g_offs[node + 1];
    float sd = g_sdst[node];

    float denom = 0.f;
    for (int base = beg; base < end; base += 32) {
        int j = base + lane;
        if (j < end) {
            int s = g_esrc[j];
            float ex = __expf(fmaxf(g_ssrc[s] + sd, 0.f));
            denom += ex;
            g_epack[j] = make_float2(__int_as_float(s), ex);
        }
    }
#pragma unroll
    for (int o = 16; o; o >>= 1) denom += __shfl_xor_sync(0xffffffffu, denom, o);
    float inv = 1.f / denom;

    for (int j = beg + lane; j < end; j += 32) {
        float2 pk = g_epack[j];
        pk.y *= inv;
        g_epack[j] = pk;
    }
}

// ---------------------------------------------------------------- aggregation
// One warp per destination node. Per edge: one uniform 8B pack load
// ({src, alpha}), one 16B fp32 row-slice load, two f32x2 FMAs. No shuffles,
// no exp, no conversions. 4-wide unroll for MLP.
__global__ void __launch_bounds__(256) aggregate_kernel(
    const float* __restrict__ h, const float* __restrict__ bias,
    float* __restrict__ out, int n, int do_relu) {
    int gt = blockIdx.x * blockDim.x + threadIdx.x;
    int node = gt >> 5, lane = gt & 31;
    if (node >= n) return;

    int beg = g_offs[node];
    int end = g_offs[node + 1];

    unsigned long long acc0 = 0ull, acc1 = 0ull;

    int j = beg;
    for (; j + 4 <= end; j += 4) {
        float2 p0 = g_epack[j + 0];
        float2 p1 = g_epack[j + 1];
        float2 p2 = g_epack[j + 2];
        float2 p3 = g_epack[j + 3];
        const ulonglong2 v0 = *(const ulonglong2*)&h[(size_t)__float_as_int(p0.x) * D + lane * 4];
        const ulonglong2 v1 = *(const ulonglong2*)&h[(size_t)__float_as_int(p1.x) * D + lane * 4];
        const ulonglong2 v2 = *(const ulonglong2*)&h[(size_t)__float_as_int(p2.x) * D + lane * 4];
        const ulonglong2 v3 = *(const ulonglong2*)&h[(size_t)__float_as_int(p3.x) * D + lane * 4];
        unsigned long long a0 = dup2(p0.y), a1 = dup2(p1.y), a2 = dup2(p2.y), a3 = dup2(p3.y);
        ffma2(acc0, a0, v0.x); ffma2(acc1, a0, v0.y);
        ffma2(acc0, a1, v1.x); ffma2(acc1, a1, v1.y);
        ffma2(acc0, a2, v2.x); ffma2(acc1, a2, v2.y);
        ffma2(acc0, a3, v3.x); ffma2(acc1, a3, v3.y);
    }
    for (; j < end; j++) {
        float2 pk = g_epack[j];
        const ulonglong2 v = *(const ulonglong2*)&h[(size_t)__float_as_int(pk.x) * D + lane * 4];
        unsigned long long a = dup2(pk.y);
        ffma2(acc0, a, v.x);
        ffma2(acc1, a, v.y);
    }

    float2 lo = *(float2*)&acc0;
    float2 hi = *(float2*)&acc1;
    float4 b4 = *(const float4*)&bias[lane * 4];
    float4 o4;
    o4.x = lo.x + b4.x;
    o4.y = lo.y + b4.y;
    o4.z = hi.x + b4.z;
    o4.w = hi.y + b4.w;
    if (do_relu) {
        o4.x = fmaxf(o4.x, 0.f);
        o4.y = fmaxf(o4.y, 0.f);
        o4.z = fmaxf(o4.z, 0.f);
        o4.w = fmaxf(o4.w, 0.f);
    }
    *(float4*)&out[(size_t)node * D + lane * 4] = o4;
}

// ---------------------------------------------------------------- launch
extern "C" void kernel_launch(void* const* d_in, const int* in_sizes, int n_in,
                              void* d_out, int out_size) {
    const float* node_x = (const float*)d_in[0];
    const int*   ei     = (const int*)d_in[1];
    const float* W1     = (const float*)d_in[2];
    const float* as1    = (const float*)d_in[3];
    const float* ad1    = (const float*)d_in[4];
    const float* b1     = (const float*)d_in[5];
    const float* W2     = (const float*)d_in[6];
    const float* as2    = (const float*)d_in[7];
    const float* ad2    = (const float*)d_in[8];
    const float* b2     = (const float*)d_in[9];
    const float* Wout   = (const float*)d_in[10];
    const float* bout   = (const float*)d_in[11];
    float* out = (float*)d_out;

    int n = in_sizes[0] / D;       // 50000
    int E = in_sizes[1] / 2;       // 1600000

    float *h_ptr, *x_ptr;
    cudaGetSymbolAddress((void**)&h_ptr, g_h);
    cudaGetSymbolAddress((void**)&x_ptr, g_x);

    const int SMEM128 = (D * 128 + 32 * D) * (int)sizeof(float);   // 80 KB
    const int SMEM64  = (D * 64 + 32 * D) * (int)sizeof(float);    // 48 KB
    cudaFuncSetAttribute(gemm_kernel<128>, cudaFuncAttributeMaxDynamicSharedMemorySize, SMEM128);
    cudaFuncSetAttribute(gemm_kernel<64>, cudaFuncAttributeMaxDynamicSharedMemorySize, SMEM64);

    int tot = E + n;

    // CSR build (shared by both layers)
    zero_deg_kernel<<<(n + 255) / 256, 256>>>(n);
    hist_kernel<<<(tot + 1023) / 1024, 256>>>(ei, E, n);
    scan_kernel<<<1, 1024>>>(n);
    scatter_kernel<<<(tot + 1023) / 1024, 256>>>(ei, E, n);

    int agg_grid = (n * 32 + 255) / 256;
    int gemm_grid = (n + 31) / 32;

    // layer 1
    gemm_kernel<128><<<gemm_grid, 128, SMEM128>>>(node_x, W1, nullptr, h_ptr, n);
    dots_kernel<<<agg_grid, 256>>>(h_ptr, as1, ad1, n);
    alpha_kernel<<<agg_grid, 256>>>(n);
    aggregate_kernel<<<agg_grid, 256>>>(h_ptr, b1, x_ptr, n, 1);

    // layer 2
    gemm_kernel<128><<<gemm_grid, 128, SMEM128>>>(x_ptr, W2, nullptr, h_ptr, n);
    dots_kernel<<<agg_grid, 256>>>(h_ptr, as2, ad2, n);
    alpha_kernel<<<agg_grid, 256>>>(n);
    aggregate_kernel<<<agg_grid, 256>>>(h_ptr, b2, x_ptr, n, 0);

    // output linear
    gemm_kernel<64><<<gemm_grid, 64, SMEM64>>>(x_ptr, Wout, bout, out, n);
}

// round 4
// speedup vs baseline: 1.3716x; 1.2620x over previous
#include <cuda_runtime.h>
#include <cuda_fp16.h>

// Problem shape (fixed per dataset)
#define NN   50000
#define EE_CAP 1650512   // E + N self loops, with margin
#define D    128
#define DOUT 64
#define SCAN_B 256

// ---- device scratch (no allocation allowed) ----
__device__ float  g_h[NN * D];      // current-layer transformed features h = x @ W (fp32)
__device__ __half g_hh[NN * D];     // fp16 copy of h for the edge gather
__device__ float  g_x[NN * D];      // aggregation output / next layer input
__device__ float  g_ssrc[NN];       // h @ att_src
__device__ float  g_sdst[NN];       // h @ att_dst
__device__ float  g_inv[NN];        // 1 / softmax denominator per node
__device__ int    g_deg[NN];
__device__ int    g_offs[NN + 1];
__device__ int    g_cursor[NN];
__device__ int    g_bsum[(NN + SCAN_B - 1) / SCAN_B];
__device__ int    g_boff[(NN + SCAN_B - 1) / SCAN_B];
__device__ int    g_esrc[EE_CAP];   // CSR-by-dst: source node per edge
__device__ float2 g_epack[EE_CAP];  // per edge: {src as int bits, exp(e) un-normalized}

// packed f32x2 fma helpers
__device__ __forceinline__ void ffma2(unsigned long long& acc,
                                      unsigned long long a,
                                      unsigned long long b) {
    asm("fma.rn.f32x2 %0, %1, %2, %0;" : "+l"(acc) : "l"(a), "l"(b));
}
__device__ __forceinline__ unsigned long long dup2(float v) {
    unsigned long long r;
    asm("mov.b64 %0, {%1, %1};" : "=l"(r) : "f"(v));
    return r;
}

// ---------------------------------------------------------------- CSR build
__global__ void zero_deg_kernel(int n) {
    int i = blockIdx.x * blockDim.x + threadIdx.x;
    if (i < n) g_deg[i] = 0;
}

__global__ void hist_kernel(const int* __restrict__ ei, int E, int n) {
    int i0 = (blockIdx.x * blockDim.x + threadIdx.x) * 4;
#pragma unroll
    for (int u = 0; u < 4; u++) {
        int i = i0 + u;
        if (i < E) atomicAdd(&g_deg[ei[E + i]], 1);
        else if (i < E + n) atomicAdd(&g_deg[i - E], 1);
    }
}

// --- coalesced 3-phase scan: block-local excl. scan -> scan of block sums -> add ---
__device__ __forceinline__ int block_excl_scan(int v, int tid, int* warp_sums) {
    int lane = tid & 31, wid = tid >> 5;
    int x = v;
#pragma unroll
    for (int o = 1; o < 32; o <<= 1) {
        int y = __shfl_up_sync(0xffffffffu, x, o);
        if (lane >= o) x += y;
    }
    if (lane == 31) warp_sums[wid] = x;
    __syncthreads();
    int base = 0;
#pragma unroll
    for (int w = 0; w < SCAN_B / 32; w++)
        if (w < wid) base += warp_sums[w];
    return base + x - v;   // exclusive
}

__global__ void scan1_kernel(int n) {
    __shared__ int ws[SCAN_B / 32];
    int tid = threadIdx.x;
    int i = blockIdx.x * SCAN_B + tid;
    int v = (i < n) ? g_deg[i] : 0;
    int ex = block_excl_scan(v, tid, ws);
    if (i < n) g_offs[i] = ex;
    if (tid == SCAN_B - 1) g_bsum[blockIdx.x] = ex + v;
}

__global__ void scan2_kernel(int nb) {
    __shared__ int ws[SCAN_B / 32];
    int tid = threadIdx.x;
    int v = (tid < nb) ? g_bsum[tid] : 0;
    int ex = block_excl_scan(v, tid, ws);
    if (tid < nb) g_boff[tid] = ex;
}

__global__ void scan3_kernel(int n, int total) {
    int i = blockIdx.x * SCAN_B + threadIdx.x;
    if (i < n) {
        int o = g_offs[i] + g_boff[blockIdx.x];
        g_offs[i] = o;
        g_cursor[i] = o;
    }
    if (i == 0) g_offs[n] = total;
}

__global__ void scatter_kernel(const int* __restrict__ ei, int E, int n) {
    int i0 = (blockIdx.x * blockDim.x + threadIdx.x) * 4;
#pragma unroll
    for (int u = 0; u < 4; u++) {
        int i = i0 + u;
        if (i < E) {
            int s = ei[i];
            int d = ei[E + i];
            int p = atomicAdd(&g_cursor[d], 1);
            g_esrc[p] = s;
        } else if (i < E + n) {
            int v = i - E;
            int p = atomicAdd(&g_cursor[v], 1);
            g_esrc[p] = v;
        }
    }
}

// ---------------------------------------------------------------- GEMM
// Y[n, COLS] = X[n, 128] @ W[128, COLS] (+ bias), FFMA2 inner product.
// Optionally emits fp16 copy Yh for the edge gather.
template <int COLS>
__global__ void gemm_kernel(const float* __restrict__ X, const float* __restrict__ W,
                            const float* __restrict__ bias, float* __restrict__ Y,
                            __half* __restrict__ Yh, int n) {
    extern __shared__ float sm[];
    float* Ws = sm;              // D * COLS
    float* Xs = sm + D * COLS;   // 32 * D
    const int CG = COLS / 4;
    int tid = threadIdx.x;
    int cg = tid % CG;
    int rg = tid / CG;           // 0..3
    int rowbase = blockIdx.x * 32;

    for (int i = tid; i < D * COLS; i += COLS) Ws[i] = W[i];
    for (int i = tid; i < 32 * D; i += COLS) {
        int r = rowbase + (i >> 7);
        Xs[i] = (r < n) ? X[(size_t)r * D + (i & 127)] : 0.f;
    }
    __syncthreads();

    unsigned long long accL[8], accH[8];
#pragma unroll
    for (int r = 0; r < 8; r++) { accL[r] = 0ull; accH[r] = 0ull; }

#pragma unroll 4
    for (int k = 0; k < D; k++) {
        ulonglong2 w2 = *(const ulonglong2*)&Ws[k * COLS + cg * 4];
#pragma unroll
        for (int rr = 0; rr < 8; rr++) {
            unsigned long long xx = dup2(Xs[(rg * 8 + rr) * D + k]);
            ffma2(accL[rr], xx, w2.x);
            ffma2(accH[rr], xx, w2.y);
        }
    }

    float4 b4 = make_float4(0.f, 0.f, 0.f, 0.f);
    if (bias) b4 = *(const float4*)&bias[cg * 4];
#pragma unroll
    for (int rr = 0; rr < 8; rr++) {
        int r = rowbase + rg * 8 + rr;
        if (r < n) {
            float2 lo = *(float2*)&accL[rr];
            float2 hi = *(float2*)&accH[rr];
            float4 o;
            o.x = lo.x + b4.x;
            o.y = lo.y + b4.y;
            o.z = hi.x + b4.z;
            o.w = hi.y + b4.w;
            *(float4*)&Y[(size_t)r * COLS + cg * 4] = o;
            if (Yh) {
                __half2 h0 = __floats2half2_rn(o.x, o.y);
                __half2 h1 = __floats2half2_rn(o.z, o.w);
                uint2 pk;
                pk.x = *(unsigned*)&h0;
                pk.y = *(unsigned*)&h1;
                *(uint2*)&Yh[(size_t)r * COLS + cg * 4] = pk;
            }
        }
    }
}

// ---------------------------------------------------------------- attention dots
__global__ void dots_kernel(const float* __restrict__ h,
                            const float* __restrict__ asrc,
                            const float* __restrict__ adst, int n) {
    int gt = blockIdx.x * blockDim.x + threadIdx.x;
    int w = gt >> 5, lane = gt & 31;
    if (w >= n) return;
    float4 hv = *(const float4*)&h[(size_t)w * D + lane * 4];
    float4 a = *(const float4*)&asrc[lane * 4];
    float4 b = *(const float4*)&adst[lane * 4];
    float p = hv.x * a.x + hv.y * a.y + hv.z * a.z + hv.w * a.w;
    float q = hv.x * b.x + hv.y * b.y + hv.z * b.z + hv.w * b.w;
#pragma unroll
    for (int o = 16; o; o >>= 1) {
        p += __shfl_xor_sync(0xffffffffu, p, o);
        q += __shfl_xor_sync(0xffffffffu, q, o);
    }
    if (lane == 0) {
        g_ssrc[w] = p;
        g_sdst[w] = q;
    }
}

// ---------------------------------------------------------------- alpha precompute
// One warp per node: per incoming edge compute exp(relu(e)) (NEG_SLOPE=0 =>
// e >= 0, exp bounded, max-shift unnecessary), write packed {src, ex} ONCE,
// store 1/denom per node (applied in aggregate epilogue).
__global__ void __launch_bounds__(256) alpha_kernel(int n) {
    int gt = blockIdx.x * blockDim.x + threadIdx.x;
    int node = gt >> 5, lane = gt & 31;
    if (node >= n) return;
    int beg = g_offs[node];
    int end = g_offs[node + 1];
    float sd = g_sdst[node];

    float denom = 0.f;
    for (int base = beg; base < end; base += 32) {
        int j = base + lane;
        if (j < end) {
            int s = g_esrc[j];
            float ex = __expf(fmaxf(g_ssrc[s] + sd, 0.f));
            denom += ex;
            g_epack[j] = make_float2(__int_as_float(s), ex);
        }
    }
#pragma unroll
    for (int o = 16; o; o >>= 1) denom += __shfl_xor_sync(0xffffffffu, denom, o);
    if (lane == 0) g_inv[node] = 1.f / denom;
}

// ---------------------------------------------------------------- aggregation
// One warp per node. Per edge: 8B pack load (uniform) + 8B fp16 row-slice
// load per lane + 2 cvt + 2 FFMA2. Normalization applied once at the end.
__global__ void __launch_bounds__(256) aggregate_kernel(
    const __half* __restrict__ hh, const float* __restrict__ bias,
    float* __restrict__ out, int n, int do_relu) {
    int gt = blockIdx.x * blockDim.x + threadIdx.x;
    int node = gt >> 5, lane = gt & 31;
    if (node >= n) return;

    int beg = g_offs[node];
    int end = g_offs[node + 1];

    unsigned long long acc0 = 0ull, acc1 = 0ull;

    int j = beg;
    for (; j + 4 <= end; j += 4) {
        float2 p0 = g_epack[j + 0];
        float2 p1 = g_epack[j + 1];
        float2 p2 = g_epack[j + 2];
        float2 p3 = g_epack[j + 3];
        uint2 v0 = *(const uint2*)&hh[(size_t)__float_as_int(p0.x) * D + lane * 4];
        uint2 v1 = *(const uint2*)&hh[(size_t)__float_as_int(p1.x) * D + lane * 4];
        uint2 v2 = *(const uint2*)&hh[(size_t)__float_as_int(p2.x) * D + lane * 4];
        uint2 v3 = *(const uint2*)&hh[(size_t)__float_as_int(p3.x) * D + lane * 4];
        float2 a0 = __half22float2(*(__half2*)&v0.x);
        float2 b0 = __half22float2(*(__half2*)&v0.y);
        float2 a1 = __half22float2(*(__half2*)&v1.x);
        float2 b1 = __half22float2(*(__half2*)&v1.y);
        float2 a2 = __half22float2(*(__half2*)&v2.x);
        float2 b2 = __half22float2(*(__half2*)&v2.y);
        float2 a3 = __half22float2(*(__half2*)&v3.x);
        float2 b3 = __half22float2(*(__half2*)&v3.y);
        unsigned long long w0 = dup2(p0.y), w1 = dup2(p1.y);
        unsigned long long w2 = dup2(p2.y), w3 = dup2(p3.y);
        ffma2(acc0, w0, *(unsigned long long*)&a0);
        ffma2(acc1, w0, *(unsigned long long*)&b0);
        ffma2(acc0, w1, *(unsigned long long*)&a1);
        ffma2(acc1, w1, *(unsigned long long*)&b1);
        ffma2(acc0, w2, *(unsigned long long*)&a2);
        ffma2(acc1, w2, *(unsigned long long*)&b2);
        ffma2(acc0, w3, *(unsigned long long*)&a3);
        ffma2(acc1, w3, *(unsigned long long*)&b3);
    }
    for (; j < end; j++) {
        float2 pk = g_epack[j];
        uint2 v = *(const uint2*)&hh[(size_t)__float_as_int(pk.x) * D + lane * 4];
        float2 a = __half22float2(*(__half2*)&v.x);
        float2 b = __half22float2(*(__half2*)&v.y);
        unsigned long long w = dup2(pk.y);
        ffma2(acc0, w, *(unsigned long long*)&a);
        ffma2(acc1, w, *(unsigned long long*)&b);
    }

    float inv = g_inv[node];
    float2 lo = *(float2*)&acc0;
    float2 hi = *(float2*)&acc1;
    float4 b4 = *(const float4*)&bias[lane * 4];
    float4 o4;
    o4.x = lo.x * inv + b4.x;
    o4.y = lo.y * inv + b4.y;
    o4.z = hi.x * inv + b4.z;
    o4.w = hi.y * inv + b4.w;
    if (do_relu) {
        o4.x = fmaxf(o4.x, 0.f);
        o4.y = fmaxf(o4.y, 0.f);
        o4.z = fmaxf(o4.z, 0.f);
        o4.w = fmaxf(o4.w, 0.f);
    }
    *(float4*)&out[(size_t)node * D + lane * 4] = o4;
}

// ---------------------------------------------------------------- launch
extern "C" void kernel_launch(void* const* d_in, const int* in_sizes, int n_in,
                              void* d_out, int out_size) {
    const float* node_x = (const float*)d_in[0];
    const int*   ei     = (const int*)d_in[1];
    const float* W1     = (const float*)d_in[2];
    const float* as1    = (const float*)d_in[3];
    const float* ad1    = (const float*)d_in[4];
    const float* b1     = (const float*)d_in[5];
    const float* W2     = (const float*)d_in[6];
    const float* as2    = (const float*)d_in[7];
    const float* ad2    = (const float*)d_in[8];
    const float* b2     = (const float*)d_in[9];
    const float* Wout   = (const float*)d_in[10];
    const float* bout   = (const float*)d_in[11];
    float* out = (float*)d_out;

    int n = in_sizes[0] / D;       // 50000
    int E = in_sizes[1] / 2;       // 1600000

    float *h_ptr, *x_ptr;
    __half* hh_ptr;
    cudaGetSymbolAddress((void**)&h_ptr, g_h);
    cudaGetSymbolAddress((void**)&x_ptr, g_x);
    cudaGetSymbolAddress((void**)&hh_ptr, g_hh);

    const int SMEM128 = (D * 128 + 32 * D) * (int)sizeof(float);   // 80 KB
    const int SMEM64  = (D * 64 + 32 * D) * (int)sizeof(float);    // 48 KB
    cudaFuncSetAttribute(gemm_kernel<128>, cudaFuncAttributeMaxDynamicSharedMemorySize, SMEM128);
    cudaFuncSetAttribute(gemm_kernel<64>, cudaFuncAttributeMaxDynamicSharedMemorySize, SMEM64);

    int tot = E + n;
    int nb = (n + SCAN_B - 1) / SCAN_B;

    // CSR build (shared by both layers)
    zero_deg_kernel<<<(n + 255) / 256, 256>>>(n);
    hist_kernel<<<(tot + 1023) / 1024, 256>>>(ei, E, n);
    scan1_kernel<<<nb, SCAN_B>>>(n);
    scan2_kernel<<<1, SCAN_B>>>(nb);
    scan3_kernel<<<nb, SCAN_B>>>(n, tot);
    scatter_kernel<<<(tot + 1023) / 1024, 256>>>(ei, E, n);

    int agg_grid = (n * 32 + 255) / 256;
    int gemm_grid = (n + 31) / 32;

    // layer 1
    gemm_kernel<128><<<gemm_grid, 128, SMEM128>>>(node_x, W1, nullptr, h_ptr, hh_ptr, n);
    dots_kernel<<<agg_grid, 256>>>(h_ptr, as1, ad1, n);
    alpha_kernel<<<agg_grid, 256>>>(n);
    aggregate_kernel<<<agg_grid, 256>>>(hh_ptr, b1, x_ptr, n, 1);

    // layer 2
    gemm_kernel<128><<<gemm_grid, 128, SMEM128>>>(x_ptr, W2, nullptr, h_ptr, hh_ptr, n);
    dots_kernel<<<agg_grid, 256>>>(h_ptr, as2, ad2, n);
    alpha_kernel<<<agg_grid, 256>>>(n);
    aggregate_kernel<<<agg_grid, 256>>>(hh_ptr, b2, x_ptr, n, 0);

    // output linear
    gemm_kernel<64><<<gemm_grid, 64, SMEM64>>>(x_ptr, Wout, bout, out, nullptr, n);
}

// round 5
// speedup vs baseline: 1.3935x; 1.0159x over previous
#include <cuda_runtime.h>
#include <cuda_fp16.h>

// Problem shape (fixed per dataset)
#define NN   50000
#define EE_CAP 1650512   // E + N self loops, with margin
#define D    128
#define DOUT 64
#define SCAN_B 256

// ---- device scratch (no allocation allowed) ----
__device__ float  g_h[NN * D];      // current-layer transformed features (fp32)
__device__ __half g_hh[NN * D];     // fp16 copy for the edge gather
__device__ float  g_x[NN * D];      // aggregation output / next layer input
__device__ float  g_ssrc[NN];       // h @ att_src
__device__ float  g_sdst[NN];       // h @ att_dst
__device__ int    g_deg[NN];
__device__ int    g_offs[NN + 1];
__device__ int    g_cursor[NN];
__device__ int    g_bsum[(NN + SCAN_B - 1) / SCAN_B];
__device__ int    g_boff[(NN + SCAN_B - 1) / SCAN_B];
__device__ int    g_esrc[EE_CAP];   // CSR-by-dst: source node per edge
__device__ float2 g_epack[EE_CAP];  // per edge: {src bits, exp(e) un-normalized}

// packed f32x2 fma helpers
__device__ __forceinline__ void ffma2(unsigned long long& acc,
                                      unsigned long long a,
                                      unsigned long long b) {
    asm("fma.rn.f32x2 %0, %1, %2, %0;" : "+l"(acc) : "l"(a), "l"(b));
}
__device__ __forceinline__ unsigned long long dup2(float v) {
    unsigned long long r;
    asm("mov.b64 %0, {%1, %1};" : "=l"(r) : "f"(v));
    return r;
}

// ---------------------------------------------------------------- CSR build
__global__ void hist_kernel(const int* __restrict__ ei, int E, int n) {
    int i0 = (blockIdx.x * blockDim.x + threadIdx.x) * 4;
#pragma unroll
    for (int u = 0; u < 4; u++) {
        int i = i0 + u;
        if (i < E) atomicAdd(&g_deg[ei[E + i]], 1);
        else if (i < E + n) atomicAdd(&g_deg[i - E], 1);
    }
}

__device__ __forceinline__ int block_excl_scan(int v, int tid, int* warp_sums) {
    int lane = tid & 31, wid = tid >> 5;
    int x = v;
#pragma unroll
    for (int o = 1; o < 32; o <<= 1) {
        int y = __shfl_up_sync(0xffffffffu, x, o);
        if (lane >= o) x += y;
    }
    if (lane == 31) warp_sums[wid] = x;
    __syncthreads();
    int base = 0;
#pragma unroll
    for (int w = 0; w < SCAN_B / 32; w++)
        if (w < wid) base += warp_sums[w];
    return base + x - v;   // exclusive
}

__global__ void scan1_kernel(int n) {
    __shared__ int ws[SCAN_B / 32];
    int tid = threadIdx.x;
    int i = blockIdx.x * SCAN_B + tid;
    int v = (i < n) ? g_deg[i] : 0;
    int ex = block_excl_scan(v, tid, ws);
    if (i < n) g_offs[i] = ex;
    if (tid == SCAN_B - 1) g_bsum[blockIdx.x] = ex + v;
}

__global__ void scan2_kernel(int nb) {
    __shared__ int ws[SCAN_B / 32];
    int tid = threadIdx.x;
    int v = (tid < nb) ? g_bsum[tid] : 0;
    int ex = block_excl_scan(v, tid, ws);
    if (tid < nb) g_boff[tid] = ex;
}

__global__ void scan3_kernel(int n, int total) {
    int i = blockIdx.x * SCAN_B + threadIdx.x;
    if (i < n) {
        int o = g_offs[i] + g_boff[blockIdx.x];
        g_offs[i] = o;
        g_cursor[i] = o;
    }
    if (i == 0) g_offs[n] = total;
}

__global__ void scatter_kernel(const int* __restrict__ ei, int E, int n) {
    int i0 = (blockIdx.x * blockDim.x + threadIdx.x) * 4;
#pragma unroll
    for (int u = 0; u < 4; u++) {
        int i = i0 + u;
        if (i < E) {
            int s = ei[i];
            int d = ei[E + i];
            int p = atomicAdd(&g_cursor[d], 1);
            g_esrc[p] = s;
        } else if (i < E + n) {
            int v = i - E;
            int p = atomicAdd(&g_cursor[v], 1);
            g_esrc[p] = v;
        }
    }
}

// ---------------------------------------------------------------- GEMM (+ fused attention dots)
// Y[n, COLS] = X[n, 128] @ W[128, COLS] (+ bias), FFMA2 inner product.
// If asrc != nullptr (COLS==128 path): also emits fp16 copy Yh and the two
// attention dot products per row via warp shfl-reduce (a warp = one row-group
// holding all 128 columns of 8 rows).
template <int COLS>
__global__ void gemm_kernel(const float* __restrict__ X, const float* __restrict__ W,
                            const float* __restrict__ bias, float* __restrict__ Y,
                            __half* __restrict__ Yh,
                            const float* __restrict__ asrc,
                            const float* __restrict__ adst, int n) {
    extern __shared__ float sm[];
    float* Ws = sm;              // D * COLS
    float* Xs = sm + D * COLS;   // 32 * D
    const int CG = COLS / 4;
    int tid = threadIdx.x;
    int cg = tid % CG;
    int rg = tid / CG;           // 0..3
    int rowbase = blockIdx.x * 32;

    for (int i = tid; i < D * COLS; i += COLS) Ws[i] = W[i];
    for (int i = tid; i < 32 * D; i += COLS) {
        int r = rowbase + (i >> 7);
        Xs[i] = (r < n) ? X[(size_t)r * D + (i & 127)] : 0.f;
    }
    __syncthreads();

    unsigned long long accL[8], accH[8];
#pragma unroll
    for (int r = 0; r < 8; r++) { accL[r] = 0ull; accH[r] = 0ull; }

#pragma unroll 4
    for (int k = 0; k < D; k++) {
        ulonglong2 w2 = *(const ulonglong2*)&Ws[k * COLS + cg * 4];
#pragma unroll
        for (int rr = 0; rr < 8; rr++) {
            unsigned long long xx = dup2(Xs[(rg * 8 + rr) * D + k]);
            ffma2(accL[rr], xx, w2.x);
            ffma2(accH[rr], xx, w2.y);
        }
    }

    float4 b4 = make_float4(0.f, 0.f, 0.f, 0.f);
    if (bias) b4 = *(const float4*)&bias[cg * 4];

    float4 av = make_float4(0.f, 0.f, 0.f, 0.f);
    float4 dv = make_float4(0.f, 0.f, 0.f, 0.f);
    if (asrc) {
        av = *(const float4*)&asrc[cg * 4];
        dv = *(const float4*)&adst[cg * 4];
    }

#pragma unroll
    for (int rr = 0; rr < 8; rr++) {
        int r = rowbase + rg * 8 + rr;
        if (r < n) {
            float2 lo = *(float2*)&accL[rr];
            float2 hi = *(float2*)&accH[rr];
            float4 o;
            o.x = lo.x + b4.x;
            o.y = lo.y + b4.y;
            o.z = hi.x + b4.z;
            o.w = hi.y + b4.w;
            *(float4*)&Y[(size_t)r * COLS + cg * 4] = o;
            if (Yh) {
                __half2 h0 = __floats2half2_rn(o.x, o.y);
                __half2 h1 = __floats2half2_rn(o.z, o.w);
                uint2 pk;
                pk.x = *(unsigned*)&h0;
                pk.y = *(unsigned*)&h1;
                *(uint2*)&Yh[(size_t)r * COLS + cg * 4] = pk;
            }
            if (asrc && COLS == 128) {
                // warp = all 32 column-groups of this row; reduce dot products
                float p = o.x * av.x + o.y * av.y + o.z * av.z + o.w * av.w;
                float q = o.x * dv.x + o.y * dv.y + o.z * dv.z + o.w * dv.w;
#pragma unroll
                for (int of = 16; of; of >>= 1) {
                    p += __shfl_xor_sync(0xffffffffu, p, of);
                    q += __shfl_xor_sync(0xffffffffu, q, of);
                }
                if (cg == 0) {
                    g_ssrc[r] = p;
                    g_sdst[r] = q;
                }
            }
        }
    }
}

// ---------------------------------------------------------------- fused alpha + aggregation
// One warp per destination node.
// Pass 1: per-edge exp(relu(e)) (NEG_SLOPE=0 => e>=0, exp bounded, max-shift
//         unnecessary), stage {src, ex} in g_epack, warp-reduce denominator.
// Pass 2: gather fp16 rows, FFMA2-accumulate, normalize once at the end.
// g_epack[beg..end) is touched only by this warp -> same-SM visibility.
__global__ void __launch_bounds__(256) gat_edge_kernel(
    const __half* __restrict__ hh, const float* __restrict__ bias,
    float* __restrict__ out, int n, int do_relu) {
    int gt = blockIdx.x * blockDim.x + threadIdx.x;
    int node = gt >> 5, lane = gt & 31;
    if (node >= n) return;

    int beg = g_offs[node];
    int end = g_offs[node + 1];
    float sd = g_sdst[node];

    float denom = 0.f;
    for (int j = beg + lane; j < end; j += 32) {
        int s = g_esrc[j];
        float ex = __expf(fmaxf(g_ssrc[s] + sd, 0.f));
        denom += ex;
        g_epack[j] = make_float2(__int_as_float(s), ex);
    }
#pragma unroll
    for (int o = 16; o; o >>= 1) denom += __shfl_xor_sync(0xffffffffu, denom, o);
    float inv = 1.f / denom;
    __syncwarp();

    unsigned long long acc0 = 0ull, acc1 = 0ull;
    int j = beg;
    for (; j + 4 <= end; j += 4) {
        float2 p0 = g_epack[j + 0];
        float2 p1 = g_epack[j + 1];
        float2 p2 = g_epack[j + 2];
        float2 p3 = g_epack[j + 3];
        uint2 v0 = *(const uint2*)&hh[(size_t)__float_as_int(p0.x) * D + lane * 4];
        uint2 v1 = *(const uint2*)&hh[(size_t)__float_as_int(p1.x) * D + lane * 4];
        uint2 v2 = *(const uint2*)&hh[(size_t)__float_as_int(p2.x) * D + lane * 4];
        uint2 v3 = *(const uint2*)&hh[(size_t)__float_as_int(p3.x) * D + lane * 4];
        float2 a0 = __half22float2(*(__half2*)&v0.x);
        float2 b0 = __half22float2(*(__half2*)&v0.y);
        float2 a1 = __half22float2(*(__half2*)&v1.x);
        float2 b1 = __half22float2(*(__half2*)&v1.y);
        float2 a2 = __half22float2(*(__half2*)&v2.x);
        float2 b2 = __half22float2(*(__half2*)&v2.y);
        float2 a3 = __half22float2(*(__half2*)&v3.x);
        float2 b3 = __half22float2(*(__half2*)&v3.y);
        unsigned long long w0 = dup2(p0.y), w1 = dup2(p1.y);
        unsigned long long w2 = dup2(p2.y), w3 = dup2(p3.y);
        ffma2(acc0, w0, *(unsigned long long*)&a0);
        ffma2(acc1, w0, *(unsigned long long*)&b0);
        ffma2(acc0, w1, *(unsigned long long*)&a1);
        ffma2(acc1, w1, *(unsigned long long*)&b1);
        ffma2(acc0, w2, *(unsigned long long*)&a2);
        ffma2(acc1, w2, *(unsigned long long*)&b2);
        ffma2(acc0, w3, *(unsigned long long*)&a3);
        ffma2(acc1, w3, *(unsigned long long*)&b3);
    }
    for (; j < end; j++) {
        float2 pk = g_epack[j];
        uint2 v = *(const uint2*)&hh[(size_t)__float_as_int(pk.x) * D + lane * 4];
        float2 a = __half22float2(*(__half2*)&v.x);
        float2 b = __half22float2(*(__half2*)&v.y);
        unsigned long long w = dup2(pk.y);
        ffma2(acc0, w, *(unsigned long long*)&a);
        ffma2(acc1, w, *(unsigned long long*)&b);
    }

    float2 lo = *(float2*)&acc0;
    float2 hi = *(float2*)&acc1;
    float4 b4 = *(const float4*)&bias[lane * 4];
    float4 o4;
    o4.x = lo.x * inv + b4.x;
    o4.y = lo.y * inv + b4.y;
    o4.z = hi.x * inv + b4.z;
    o4.w = hi.y * inv + b4.w;
    if (do_relu) {
        o4.x = fmaxf(o4.x, 0.f);
        o4.y = fmaxf(o4.y, 0.f);
        o4.z = fmaxf(o4.z, 0.f);
        o4.w = fmaxf(o4.w, 0.f);
    }
    *(float4*)&out[(size_t)node * D + lane * 4] = o4;
}

// ---------------------------------------------------------------- launch
extern "C" void kernel_launch(void* const* d_in, const int* in_sizes, int n_in,
                              void* d_out, int out_size) {
    const float* node_x = (const float*)d_in[0];
    const int*   ei     = (const int*)d_in[1];
    const float* W1     = (const float*)d_in[2];
    const float* as1    = (const float*)d_in[3];
    const float* ad1    = (const float*)d_in[4];
    const float* b1     = (const float*)d_in[5];
    const float* W2     = (const float*)d_in[6];
    const float* as2    = (const float*)d_in[7];
    const float* ad2    = (const float*)d_in[8];
    const float* b2     = (const float*)d_in[9];
    const float* Wout   = (const float*)d_in[10];
    const float* bout   = (const float*)d_in[11];
    float* out = (float*)d_out;

    int n = in_sizes[0] / D;       // 50000
    int E = in_sizes[1] / 2;       // 1600000

    float *h_ptr, *x_ptr;
    __half* hh_ptr;
    int* deg_ptr;
    cudaGetSymbolAddress((void**)&h_ptr, g_h);
    cudaGetSymbolAddress((void**)&x_ptr, g_x);
    cudaGetSymbolAddress((void**)&hh_ptr, g_hh);
    cudaGetSymbolAddress((void**)&deg_ptr, g_deg);

    const int SMEM128 = (D * 128 + 32 * D) * (int)sizeof(float);   // 80 KB
    const int SMEM64  = (D * 64 + 32 * D) * (int)sizeof(float);    // 48 KB
    cudaFuncSetAttribute(gemm_kernel<128>, cudaFuncAttributeMaxDynamicSharedMemorySize, SMEM128);
    cudaFuncSetAttribute(gemm_kernel<64>, cudaFuncAttributeMaxDynamicSharedMemorySize, SMEM64);

    int tot = E + n;
    int nb = (n + SCAN_B - 1) / SCAN_B;

    // CSR build (shared by both layers)
    cudaMemsetAsync(deg_ptr, 0, (size_t)n * sizeof(int), 0);
    hist_kernel<<<(tot + 1023) / 1024, 256>>>(ei, E, n);
    scan1_kernel<<<nb, SCAN_B>>>(n);
    scan2_kernel<<<1, SCAN_B>>>(nb);
    scan3_kernel<<<nb, SCAN_B>>>(n, tot);
    scatter_kernel<<<(tot + 1023) / 1024, 256>>>(ei, E, n);

    int agg_grid = (n * 32 + 255) / 256;
    int gemm_grid = (n + 31) / 32;

    // layer 1 (GEMM + fused dots, then fused alpha+aggregate)
    gemm_kernel<128><<<gemm_grid, 128, SMEM128>>>(node_x, W1, nullptr, h_ptr, hh_ptr, as1, ad1, n);
    gat_edge_kernel<<<agg_grid, 256>>>(hh_ptr, b1, x_ptr, n, 1);

    // layer 2
    gemm_kernel<128><<<gemm_grid, 128, SMEM128>>>(x_ptr, W2, nullptr, h_ptr, hh_ptr, as2, ad2, n);
    gat_edge_kernel<<<agg_grid, 256>>>(hh_ptr, b2, x_ptr, n, 0);

    // output linear
    gemm_kernel<64><<<gemm_grid, 64, SMEM64>>>(x_ptr, Wout, bout, out, nullptr, nullptr, nullptr, n);
}